// round 10
// baseline (speedup 1.0000x reference)
#include <cuda_runtime.h>
#include <cuda_bf16.h>
#include <math_constants.h>

#define BATCH 2048
#define TLEN  4096
#define NSIG  7
#define PRED  64
#define TPB   256
#define NW    (TPB / 32)

typedef unsigned long long ull;

__constant__ float c_lrs[NSIG] = {0.01f, 0.08f, 0.1f, 0.15f, 0.2f, 0.25f, 1.0f};

// Scratch (static __device__ — no allocations allowed)
__device__ float g_errs[BATCH * NSIG];
__device__ float g_levels[BATCH * NSIG];
__device__ int   g_bestRow[BATCH];
__device__ int   g_sigIdx[BATCH];
__device__ float g_filt[(size_t)BATCH * TLEN];   // only ~log2(B) rows ever written

// Grid barrier state (generation counter; count self-resets each barrier)
__device__ unsigned g_barCount = 0;
__device__ volatile unsigned g_barGen = 0;

__device__ __forceinline__ void grid_barrier(int nblocks) {
    __syncthreads();
    if (threadIdx.x == 0) {
        unsigned gen = g_barGen;
        __threadfence();                                  // publish my phase's stores
        if (atomicAdd(&g_barCount, 1u) == (unsigned)(nblocks - 1)) {
            g_barCount = 0;
            __threadfence();
            g_barGen = gen + 1;                           // release
        } else {
            while (g_barGen == gen) __nanosleep(64);
        }
        __threadfence();                                  // acquire
    }
    __syncthreads();
}

// ---- packed f32x2 helpers (Blackwell; PTX-only path) -----------------------
__device__ __forceinline__ ull pack2(float lo, float hi) {
    ull r; asm("mov.b64 %0, {%1, %2};" : "=l"(r) : "f"(lo), "f"(hi)); return r;
}
__device__ __forceinline__ void unpack2(ull v, float& lo, float& hi) {
    asm("mov.b64 {%0, %1}, %2;" : "=f"(lo), "=f"(hi) : "l"(v));
}
__device__ __forceinline__ ull ffma2(ull a, ull b, ull c) {
    ull d; asm("fma.rn.f32x2 %0, %1, %2, %3;" : "=l"(d) : "l"(a), "l"(b), "l"(c)); return d;
}
__device__ __forceinline__ ull fmul2(ull a, ull b) {
    ull d; asm("mul.rn.f32x2 %0, %1, %2;" : "=l"(d) : "l"(a), "l"(b)); return d;
}

// ---------------------------------------------------------------------------
// ONE persistent kernel. Phases separated by grid barriers:
//  1. scan   : innovation-form EWMA scan, all rows, all 7 sigmas (R8 math)
//  2. pick   : block 0 — argmin over sigmas + strict-< prefix min over rows
//  3. filt   : rows with bestRow[r]==r write the filtered series (prior level)
//  4. diff   : grid-stride out = data - filt[bestRow], + broadcast preds
// __launch_bounds__(256,4) + ~24KB smem guarantees nblocks co-residency.
// ---------------------------------------------------------------------------
__global__ void __launch_bounds__(TPB, 4)
aligator_persistent(const float* __restrict__ data, float* __restrict__ out,
                    int nblocks) {
    __shared__ float sLast[TPB];
    __shared__ ull   sWA[NW * 3], sWC[NW * 3];
    __shared__ float sE[NSIG][TPB];
    __shared__ float sFA[NW], sFC[NW];
    __shared__ float sY0;
    __shared__ float sMin[BATCH];          // 8KB (pick, block 0 only)
    __shared__ int   sIdx[BATCH];          // 8KB

    int t = threadIdx.x;
    int lane = t & 31;
    int w = t >> 5;

    // ===================== Phase 1: scan =====================
    for (int r = blockIdx.x; r < BATCH; r += nblocks) {
        const float4* row = (const float4*)(data + (size_t)r * TLEN);
        float4 v[4];                       // 16 floats, time-contiguous
#pragma unroll
        for (int i = 0; i < 4; i++) v[i] = __ldg(&row[t * 4 + i]);

        sLast[t] = v[3].w;
        __syncthreads();
        float yprev = t ? sLast[t - 1] : v[0].x;   // dy_0 = 0 for t==0
        float ylast = v[3].w;

        ull A1[3];
        A1[0] = pack2(0.99f, 0.92f);
        A1[1] = pack2(0.90f, 0.85f);
        A1[2] = pack2(0.80f, 0.75f);

        // phase1: Horner of dy; dy stored back into v
        ull H[3] = {0ull, 0ull, 0ull};
        float yp = yprev;
#pragma unroll
        for (int i = 0; i < 4; i++) {
#define P1STEP(REF) { float yy = (REF); float dl = yy - yp; yp = yy; (REF) = dl; \
            ull d2 = pack2(dl, dl);                       \
            H[0] = ffma2(A1[0], H[0], d2);                \
            H[1] = ffma2(A1[1], H[1], d2);                \
            H[2] = ffma2(A1[2], H[2], d2); }
            P1STEP(v[i].x) P1STEP(v[i].y) P1STEP(v[i].z) P1STEP(v[i].w)
#undef P1STEP
        }
        ull A[3], C[3];
#pragma unroll
        for (int p = 0; p < 3; p++) {
            ull a = A1[p];                 // a^16 via 4 packed squarings
            a = fmul2(a, a); a = fmul2(a, a); a = fmul2(a, a); a = fmul2(a, a);
            A[p] = a;
            C[p] = H[p];
        }

        // inclusive warp scan of transfers
#pragma unroll
        for (int p = 0; p < 3; p++) {
#pragma unroll
            for (int off = 1; off < 32; off <<= 1) {
                ull pa = __shfl_up_sync(0xffffffffu, A[p], off);
                ull pc = __shfl_up_sync(0xffffffffu, C[p], off);
                if (lane >= off) { C[p] = ffma2(A[p], pc, C[p]); A[p] = fmul2(A[p], pa); }
            }
            if (lane == 31) { sWA[w * 3 + p] = A[p]; sWC[w * 3 + p] = C[p]; }
        }
        __syncthreads();

        ull Dent[3];
#pragma unroll
        for (int p = 0; p < 3; p++) {
            ull pc = 0ull;                 // d_init = 0
#pragma unroll
            for (int j = 0; j < NW - 1; j++)
                if (j < w) pc = ffma2(sWA[j * 3 + p], pc, sWC[j * 3 + p]);
            ull eA = __shfl_up_sync(0xffffffffu, A[p], 1);
            ull eC = __shfl_up_sync(0xffffffffu, C[p], 1);
            Dent[p] = (lane == 0) ? pc : ffma2(eA, pc, eC);
        }

        // phase2: d-recurrence + error accumulation
        ull D[3] = {Dent[0], Dent[1], Dent[2]};
        ull E[3] = {0ull, 0ull, 0ull};
        float e6 = 0.0f;
#pragma unroll
        for (int i = 0; i < 4; i++) {
#define P2STEP(REF) { float dl = (REF); ull d2 = pack2(dl, dl);  \
            D[0] = ffma2(A1[0], D[0], d2); E[0] = ffma2(D[0], D[0], E[0]); \
            D[1] = ffma2(A1[1], D[1], d2); E[1] = ffma2(D[1], D[1], E[1]); \
            D[2] = ffma2(A1[2], D[2], d2); E[2] = ffma2(D[2], D[2], E[2]); \
            e6 = fmaf(dl, dl, e6); }
            P2STEP(v[i].x) P2STEP(v[i].y) P2STEP(v[i].z) P2STEP(v[i].w)
#undef P2STEP
        }

        float ev[NSIG];
        unpack2(E[0], ev[0], ev[1]);
        unpack2(E[1], ev[2], ev[3]);
        unpack2(E[2], ev[4], ev[5]);
        ev[6] = e6;
#pragma unroll
        for (int q = 0; q < NSIG; q++) sE[q][t] = ev[q];

        if (t == TPB - 1) {                // level_final = y_last - a*d_last
            float d0, d1;
            unpack2(D[0], d0, d1);
            g_levels[r * NSIG + 0] = fmaf(-0.99f, d0, ylast);
            g_levels[r * NSIG + 1] = fmaf(-0.92f, d1, ylast);
            unpack2(D[1], d0, d1);
            g_levels[r * NSIG + 2] = fmaf(-0.90f, d0, ylast);
            g_levels[r * NSIG + 3] = fmaf(-0.85f, d1, ylast);
            unpack2(D[2], d0, d1);
            g_levels[r * NSIG + 4] = fmaf(-0.80f, d0, ylast);
            g_levels[r * NSIG + 5] = fmaf(-0.75f, d1, ylast);
            g_levels[r * NSIG + 6] = ylast;    // sigma=1
        }
        __syncthreads();

        if (t < 128) {
#pragma unroll
            for (int q = 0; q < NSIG; q++) sE[q][t] += sE[q][t + 128];
        }
        __syncthreads();
        if (t < 64) {
#pragma unroll
            for (int q = 0; q < NSIG; q++) sE[q][t] += sE[q][t + 64];
        }
        __syncthreads();
        if (t < 32) {
#pragma unroll
            for (int q = 0; q < NSIG; q++) {
                float x = sE[q][t] + sE[q][t + 32];
#pragma unroll
                for (int off = 16; off > 0; off >>= 1)
                    x += __shfl_down_sync(0xffffffffu, x, off);
                if (t == 0) g_errs[r * NSIG + q] = x * (1.0f / (float)TLEN);
            }
        }
        __syncthreads();                   // protect sLast/sE before next row
    }

    grid_barrier(nblocks);

    // ===================== Phase 2: pick (block 0) =====================
    if (blockIdx.x == 0) {
        for (int b = t; b < BATCH; b += TPB) {
            const float* e = g_errs + b * NSIG;
            float best = e[0]; int bi = 0;
#pragma unroll
            for (int s = 1; s < NSIG; s++) {
                float vv = e[s];
                if (vv < best) { best = vv; bi = s; }
            }
            sMin[b] = best; sIdx[b] = bi;
        }
        __syncthreads();

        if (t < 32) {
            float carryV = CUDART_INF_F;
            int   carryR = 0;
            for (int c = 0; c < BATCH / 32; c++) {
                int b = c * 32 + lane;
                float vv = sMin[b];
                int   rr = b;
#pragma unroll
                for (int off = 1; off < 32; off <<= 1) {
                    float pv = __shfl_up_sync(0xffffffffu, vv, off);
                    int   pr = __shfl_up_sync(0xffffffffu, rr, off);
                    if (lane >= off && !(vv < pv)) { vv = pv; rr = pr; }
                }
                if (!(vv < carryV)) { vv = carryV; rr = carryR; }
                g_bestRow[b] = rr;
                g_sigIdx[b]  = sIdx[rr];
                carryV = __shfl_sync(0xffffffffu, vv, 31);
                carryR = __shfl_sync(0xffffffffu, rr, 31);
            }
        }
    }

    grid_barrier(nblocks);

    // ===================== Phase 3: filt (best rows only) =====================
    for (int r = blockIdx.x; r < BATCH; r += nblocks) {
        if (g_bestRow[r] != r) continue;   // uniform across block

        float sigma = c_lrs[g_sigIdx[r]];
        float a = 1.0f - sigma;

        const float4* row = (const float4*)(data + (size_t)r * TLEN);
        float4 v[4];
#pragma unroll
        for (int i = 0; i < 4; i++) v[i] = __ldg(&row[t * 4 + i]);

        if (t == 0) sY0 = v[0].x;
        __syncthreads();
        float y0 = sY0;

        float H = 0.0f;
#pragma unroll
        for (int i = 0; i < 4; i++) {
            H = fmaf(a, H, v[i].x); H = fmaf(a, H, v[i].y);
            H = fmaf(a, H, v[i].z); H = fmaf(a, H, v[i].w);
        }
        float A = a;                       // a^16 via 4 squarings
        A *= A; A *= A; A *= A; A *= A;
        float C = sigma * H;

        // warp scan of transfers
#pragma unroll
        for (int off = 1; off < 32; off <<= 1) {
            float pa = __shfl_up_sync(0xffffffffu, A, off);
            float pc = __shfl_up_sync(0xffffffffu, C, off);
            if (lane >= off) { C = fmaf(A, pc, C); A *= pa; }
        }
        if (lane == 31) { sFA[w] = A; sFC[w] = C; }
        __syncthreads();

        float pa = 1.0f, pc = 0.0f;
#pragma unroll
        for (int j = 0; j < NW - 1; j++) {
            if (j < w) { pc = fmaf(sFA[j], pc, sFC[j]); pa *= sFA[j]; }
        }
        float eA = __shfl_up_sync(0xffffffffu, A, 1);
        float eC = __shfl_up_sync(0xffffffffu, C, 1);
        float Aex, Cex;
        if (lane == 0) { Aex = pa; Cex = pc; }
        else           { Aex = eA * pa; Cex = fmaf(eA, pc, eC); }
        float L = fmaf(Aex, y0, Cex);

        float4* o = (float4*)(g_filt + (size_t)r * TLEN);
#pragma unroll
        for (int i = 0; i < 4; i++) {
            float4 y = v[i];
            float4 f;
            f.x = L; L = fmaf(sigma, y.x - L, L);
            f.y = L; L = fmaf(sigma, y.y - L, L);
            f.z = L; L = fmaf(sigma, y.z - L, L);
            f.w = L; L = fmaf(sigma, y.w - L, L);
            o[t * 4 + i] = f;
        }
        __syncthreads();
    }

    grid_barrier(nblocks);

    // ===================== Phase 4: diff + preds =====================
    const int rowq = TLEN / 4;             // 1024 float4 per row
    int stride = nblocks * TPB;
    for (int i = blockIdx.x * TPB + t; i < BATCH * rowq; i += stride) {
        int b = i >> 10;
        int c = i & 1023;
        int rr = g_bestRow[b];
        float4 d = __ldcs((const float4*)data + i);
        float4 f = __ldg((const float4*)g_filt + (size_t)rr * rowq + c);
        float4 o;
        o.x = d.x - f.x; o.y = d.y - f.y; o.z = d.z - f.z; o.w = d.w - f.w;
        __stcs((float4*)out + i, o);
    }
    for (int i = blockIdx.x * TPB + t; i < BATCH * (PRED / 4); i += stride) {
        int b = i >> 4;
        float val = g_levels[b * NSIG + g_sigIdx[b]];
        float4 o = make_float4(val, val, val, val);
        __stcs((float4*)out + BATCH * rowq + i, o);
    }
}

// ---------------------------------------------------------------------------
extern "C" void kernel_launch(void* const* d_in, const int* in_sizes, int n_in,
                              void* d_out, int out_size) {
    const float* data = (const float*)d_in[0];
    float* out = (float*)d_out;

    int dev = 0;
    cudaGetDevice(&dev);
    int sms = 0;
    cudaDeviceGetAttribute(&sms, cudaDevAttrMultiProcessorCount, dev);
    int maxb = 0;
    cudaOccupancyMaxActiveBlocksPerMultiprocessor(&maxb, aligator_persistent, TPB, 0);
    if (maxb < 1) maxb = 1;
    int nb = sms * maxb;
    if (nb > BATCH) nb = BATCH;
    if (nb < 1) nb = 1;

    aligator_persistent<<<nb, TPB>>>(data, out, nb);
}

// round 11
// speedup vs baseline: 1.2508x; 1.2508x over previous
#include <cuda_runtime.h>
#include <cuda_bf16.h>
#include <math_constants.h>

#define BATCH 2048
#define TLEN  4096
#define NSIG  7
#define PRED  64

typedef unsigned long long ull;

__constant__ float c_lrs[NSIG] = {0.01f, 0.08f, 0.1f, 0.15f, 0.2f, 0.25f, 1.0f};

// Scratch (static __device__ — no allocations allowed)
__device__ float g_errs[BATCH * NSIG];
__device__ float g_levels[BATCH * NSIG];
__device__ int   g_bestRow[BATCH];
__device__ int   g_sigIdx[BATCH];
__device__ float g_filt[(size_t)BATCH * TLEN];   // only ~log2(B) rows ever written
__device__ unsigned g_scanDone = 0;              // last-block counter (self-resets)

// ---- packed f32x2 helpers (Blackwell; PTX-only path) -----------------------
__device__ __forceinline__ ull pack2(float lo, float hi) {
    ull r; asm("mov.b64 %0, {%1, %2};" : "=l"(r) : "f"(lo), "f"(hi)); return r;
}
__device__ __forceinline__ void unpack2(ull v, float& lo, float& hi) {
    asm("mov.b64 {%0, %1}, %2;" : "=f"(lo), "=f"(hi) : "l"(v));
}
__device__ __forceinline__ ull ffma2(ull a, ull b, ull c) {
    ull d; asm("fma.rn.f32x2 %0, %1, %2, %3;" : "=l"(d) : "l"(a), "l"(b), "l"(c)); return d;
}
__device__ __forceinline__ ull fmul2(ull a, ull b) {
    ull d; asm("mul.rn.f32x2 %0, %1, %2;" : "=l"(d) : "l"(a), "l"(b)); return d;
}

// ---------------------------------------------------------------------------
// K1: innovation-form scan + LAST-BLOCK PICK. 256 threads/block, 16 elems/
// thread. Constant-A scan: the chunk transfer A = a^16 is input-independent,
// so every Hillis-Steele multiplier is the constant a^(16*off) -> no A
// shuffles, no A scan; Aex = a^(16*lane) from interleaved conditional
// squarings. Scan arithmetic cannot perturb the final output (feeds only the
// discrete argmin; proven in R8).
// ---------------------------------------------------------------------------
__global__ void __launch_bounds__(256) scan_pick_kernel(const float* __restrict__ data) {
    constexpr int TPB = 256;
    constexpr int NW  = TPB / 32;          // 8 warps
    __shared__ float sLast[TPB];
    __shared__ ull   sWC[NW * 3];
    __shared__ float sE[NSIG][TPB];
    __shared__ float sMin[BATCH];          // pick (last block only)
    __shared__ int   sIdx[BATCH];
    __shared__ int   sIsLast;

    int r = blockIdx.x;
    int t = threadIdx.x;
    int lane = t & 31;
    int w = t >> 5;

    const float4* row = (const float4*)(data + (size_t)r * TLEN);
    float4 v[4];                           // 16 floats, time-contiguous
#pragma unroll
    for (int i = 0; i < 4; i++) v[i] = __ldg(&row[t * 4 + i]);

    sLast[t] = v[3].w;
    __syncthreads();
    float yprev = t ? sLast[t - 1] : v[0].x;   // dy_0 = 0 for t==0
    float ylast = v[3].w;

    ull A1[3];
    A1[0] = pack2(0.99f, 0.92f);
    A1[1] = pack2(0.90f, 0.85f);
    A1[2] = pack2(0.80f, 0.75f);

    // --- phase1: Horner of dy per pair; dy stored back into v ---------------
    ull H[3] = {0ull, 0ull, 0ull};
    float yp = yprev;
#pragma unroll
    for (int i = 0; i < 4; i++) {
#define P1STEP(REF) { float yy = (REF); float dl = yy - yp; yp = yy; (REF) = dl; \
        ull d2 = pack2(dl, dl);                       \
        H[0] = ffma2(A1[0], H[0], d2);                \
        H[1] = ffma2(A1[1], H[1], d2);                \
        H[2] = ffma2(A1[2], H[2], d2); }
        P1STEP(v[i].x) P1STEP(v[i].y) P1STEP(v[i].z) P1STEP(v[i].w)
#undef P1STEP
    }

    // Ak = a^16 (4 packed squarings); C = chunk transfer constant term
    ull Ak[3], C[3], Aex[3];
    ull ONE2 = pack2(1.0f, 1.0f);
#pragma unroll
    for (int p = 0; p < 3; p++) {
        ull a = A1[p];
        a = fmul2(a, a); a = fmul2(a, a); a = fmul2(a, a); a = fmul2(a, a);
        Ak[p] = a;                         // a^16
        C[p]  = H[p];                      // no sigma multiply in d-form
        Aex[p] = ONE2;
    }

    // --- constant-A warp scan: only C is shuffled ----------------------------
#pragma unroll
    for (int off = 1; off < 32; off <<= 1) {
#pragma unroll
        for (int p = 0; p < 3; p++) {
            ull pc = __shfl_up_sync(0xffffffffu, C[p], off);
            if (lane >= off) C[p] = ffma2(Ak[p], pc, C[p]);   // Ak = a^(16*off)
            if (lane & off)  Aex[p] = fmul2(Aex[p], Ak[p]);   // -> a^(16*lane)
            Ak[p] = fmul2(Ak[p], Ak[p]);
        }
    }
    // now Ak = a^512 (per-warp total transfer coefficient, constant)
    if (lane == 31) {
#pragma unroll
        for (int p = 0; p < 3; p++) sWC[w * 3 + p] = C[p];
    }
    __syncthreads();

    // entry d: cross-warp fold (d_init = 0, constant a^512) + in-warp exclusive
    ull Dent[3];
#pragma unroll
    for (int p = 0; p < 3; p++) {
        ull pc = 0ull;
#pragma unroll
        for (int j = 0; j < NW - 1; j++)
            if (j < w) pc = ffma2(Ak[p], pc, sWC[j * 3 + p]);
        ull eC = __shfl_up_sync(0xffffffffu, C[p], 1);
        Dent[p] = lane ? ffma2(Aex[p], pc, eC) : pc;
    }

    // --- phase2: d-recurrence + error accumulation --------------------------
    ull D[3] = {Dent[0], Dent[1], Dent[2]};
    ull E[3] = {0ull, 0ull, 0ull};
    float e6 = 0.0f;
#pragma unroll
    for (int i = 0; i < 4; i++) {
#define P2STEP(REF) { float dl = (REF); ull d2 = pack2(dl, dl);  \
        D[0] = ffma2(A1[0], D[0], d2); E[0] = ffma2(D[0], D[0], E[0]); \
        D[1] = ffma2(A1[1], D[1], d2); E[1] = ffma2(D[1], D[1], E[1]); \
        D[2] = ffma2(A1[2], D[2], d2); E[2] = ffma2(D[2], D[2], E[2]); \
        e6 = fmaf(dl, dl, e6); }
        P2STEP(v[i].x) P2STEP(v[i].y) P2STEP(v[i].z) P2STEP(v[i].w)
#undef P2STEP
    }

    float ev[NSIG];
    unpack2(E[0], ev[0], ev[1]);
    unpack2(E[1], ev[2], ev[3]);
    unpack2(E[2], ev[4], ev[5]);
    ev[6] = e6;
#pragma unroll
    for (int q = 0; q < NSIG; q++) sE[q][t] = ev[q];

    if (t == TPB - 1) {                    // level_final = y_last - a*d_last
        float d0, d1;
        unpack2(D[0], d0, d1);
        g_levels[r * NSIG + 0] = fmaf(-0.99f, d0, ylast);
        g_levels[r * NSIG + 1] = fmaf(-0.92f, d1, ylast);
        unpack2(D[1], d0, d1);
        g_levels[r * NSIG + 2] = fmaf(-0.90f, d0, ylast);
        g_levels[r * NSIG + 3] = fmaf(-0.85f, d1, ylast);
        unpack2(D[2], d0, d1);
        g_levels[r * NSIG + 4] = fmaf(-0.80f, d0, ylast);
        g_levels[r * NSIG + 5] = fmaf(-0.75f, d1, ylast);
        g_levels[r * NSIG + 6] = ylast;    // sigma=1
    }
    __syncthreads();

    if (t < 128) {
#pragma unroll
        for (int q = 0; q < NSIG; q++) sE[q][t] += sE[q][t + 128];
    }
    __syncthreads();
    if (t < 64) {
#pragma unroll
        for (int q = 0; q < NSIG; q++) sE[q][t] += sE[q][t + 64];
    }
    __syncthreads();
    if (t < 32) {
#pragma unroll
        for (int q = 0; q < NSIG; q++) {
            float x = sE[q][t] + sE[q][t + 32];
#pragma unroll
            for (int off = 16; off > 0; off >>= 1)
                x += __shfl_down_sync(0xffffffffu, x, off);
            if (t == 0) g_errs[r * NSIG + q] = x * (1.0f / (float)TLEN);
        }
    }

    // ===== last-block pick (threadfence reduction pattern) =====
    __threadfence();                       // publish this block's errs/levels
    __syncthreads();
    if (t == 0) {
        unsigned old = atomicAdd(&g_scanDone, 1u);
        sIsLast = (old == (unsigned)(BATCH - 1));
        if (sIsLast) {
            g_scanDone = 0;                // reset for next graph replay
            __threadfence();               // acquire all blocks' writes
        }
    }
    __syncthreads();
    if (!sIsLast) return;

    for (int b = t; b < BATCH; b += TPB) {
        const float* e = g_errs + b * NSIG;
        float best = e[0]; int bi = 0;
#pragma unroll
        for (int s = 1; s < NSIG; s++) {
            float vv = e[s];
            if (vv < best) { best = vv; bi = s; }
        }
        sMin[b] = best; sIdx[b] = bi;
    }
    __syncthreads();

    if (t < 32) {
        float carryV = CUDART_INF_F;
        int   carryR = 0;
        for (int c = 0; c < BATCH / 32; c++) {
            int b = c * 32 + lane;
            float vv = sMin[b];
            int   rr = b;
#pragma unroll
            for (int off = 1; off < 32; off <<= 1) {
                float pv = __shfl_up_sync(0xffffffffu, vv, off);
                int   pr = __shfl_up_sync(0xffffffffu, rr, off);
                if (lane >= off && !(vv < pv)) { vv = pv; rr = pr; }
            }
            if (!(vv < carryV)) { vv = carryV; rr = carryR; }
            g_bestRow[b] = rr;
            g_sigIdx[b]  = sIdx[rr];
            carryV = __shfl_sync(0xffffffffu, vv, 31);
            carryR = __shfl_sync(0xffffffffu, rr, 31);
        }
    }
}

// ---------------------------------------------------------------------------
// K2: recompute & store the filtered series only for rows that are ever
// "best" (bestRow[r] == r); chunked scan, 128 threads. filt is PRIOR level.
// (level-form, proven output rounding; only ~log2(B) blocks do work)
// ---------------------------------------------------------------------------
__global__ void __launch_bounds__(128) filt_kernel(const float* __restrict__ data) {
    constexpr int TPB = 128;
    constexpr int EPT = TLEN / TPB;       // 32 elements per thread
    __shared__ float sA[TPB], sC[TPB];
    __shared__ float s_y0;

    int r = blockIdx.x;
    if (g_bestRow[r] != r) return;        // uniform across block
    int t = threadIdx.x;

    float sigma = c_lrs[g_sigIdx[r]];
    float a = 1.0f - sigma;

    const float4* row = (const float4*)(data + (size_t)r * TLEN);
    float4 v[EPT / 4];
#pragma unroll
    for (int i = 0; i < EPT / 4; i++) v[i] = __ldg(&row[t * (EPT / 4) + i]);

    if (t == 0) s_y0 = v[0].x;
    __syncthreads();
    float y0 = s_y0;

    float H = 0.0f;
#pragma unroll
    for (int i = 0; i < EPT / 4; i++) {
        H = fmaf(a, H, v[i].x); H = fmaf(a, H, v[i].y);
        H = fmaf(a, H, v[i].z); H = fmaf(a, H, v[i].w);
    }
    float A = a;                           // a^32 via 5 squarings
    A *= A; A *= A; A *= A; A *= A; A *= A;
    float C = sigma * H;

    sA[t] = A; sC[t] = C;
    __syncthreads();
#pragma unroll
    for (int off = 1; off < TPB; off <<= 1) {
        float pa = 1.0f, pc = 0.0f;
        if (t >= off) { pa = sA[t - off]; pc = sC[t - off]; }
        __syncthreads();
        if (t >= off) { sC[t] = fmaf(sA[t], pc, sC[t]); sA[t] *= pa; }
        __syncthreads();
    }
    float L = (t == 0) ? y0 : fmaf(sA[t - 1], y0, sC[t - 1]);

    float4* out = (float4*)(g_filt + (size_t)r * TLEN) + t * (EPT / 4);
#pragma unroll
    for (int i = 0; i < EPT / 4; i++) {
        float4 y = v[i];
        float4 f;
        f.x = L; L = fmaf(sigma, y.x - L, L);
        f.y = L; L = fmaf(sigma, y.y - L, L);
        f.z = L; L = fmaf(sigma, y.z - L, L);
        f.w = L; L = fmaf(sigma, y.w - L, L);
        out[i] = f;
    }
}

// ---------------------------------------------------------------------------
// K3: out[b][t] = data[b][t] - filt[bestRow[b]][t]; first 32K threads also
// write the broadcast preds block. Pure streaming, max MLP (proven 12.0us).
// ---------------------------------------------------------------------------
__global__ void __launch_bounds__(256) diff_kernel(const float* __restrict__ data,
                                                   float* __restrict__ out) {
    const int rowq = TLEN / 4;
    int i = blockIdx.x * blockDim.x + threadIdx.x;
    if (i < BATCH * rowq) {
        int b = i / rowq;
        int c = i - b * rowq;
        int r = g_bestRow[b];
        float4 d = __ldcs((const float4*)data + i);
        float4 f = __ldg((const float4*)g_filt + (size_t)r * rowq + c);
        float4 o;
        o.x = d.x - f.x; o.y = d.y - f.y; o.z = d.z - f.z; o.w = d.w - f.w;
        __stcs((float4*)out + i, o);
    }
    if (i < BATCH * (PRED / 4)) {          // preds: 16 float4 per row
        int b = i >> 4;
        float val = g_levels[b * NSIG + g_sigIdx[b]];
        float4 o = make_float4(val, val, val, val);
        __stcs((float4*)out + BATCH * rowq + i, o);
    }
}

// ---------------------------------------------------------------------------
extern "C" void kernel_launch(void* const* d_in, const int* in_sizes, int n_in,
                              void* d_out, int out_size) {
    const float* data = (const float*)d_in[0];
    float* out = (float*)d_out;

    scan_pick_kernel<<<BATCH, 256>>>(data);
    filt_kernel<<<BATCH, 128>>>(data);
    {
        int nq = BATCH * (TLEN / 4);             // float4 count
        diff_kernel<<<(nq + 255) / 256, 256>>>(data, out);
    }
}